// round 13
// baseline (speedup 1.0000x reference)
#include <cuda_runtime.h>
#include <cuda_bf16.h>
#include <cstdint>

#define HID   1024
#define BATCH 16
#define SEQ   2048
#define MROWS (BATCH * SEQ)   // 32768

// ---------------- scratch (device globals: no allocation allowed) ------------
// g_qh / g_scores are zero at process start (.bss) and re-zeroed by softmax
// each launch AFTER their last reader -> atomic-accumulate targets are always
// zeroed when prep/gemm run, on the correctness call and on every replay.
__device__ __nv_bfloat16 g_keys_bf16[(size_t)MROWS * HID];   // 64 MB
__device__ __nv_bfloat16 g_w1bT[(size_t)HID * HID];          // 2 MB, [N,K] = W1[H+k, n]
__device__ float         g_qh[BATCH * HID];                  // b1 + q @ W1_top
__device__ float         g_scores[MROWS];

// ---------------- helpers ----------------------------------------------------
__device__ __forceinline__ uint32_t smem_to_u32(const void* p) {
    uint32_t a;
    asm("{ .reg .u64 t; cvta.to.shared.u64 t, %1; cvt.u32.u64 %0, t; }" : "=r"(a) : "l"(p));
    return a;
}
__device__ __forceinline__ void cp16(uint32_t s, const void* g) {
    asm volatile("cp.async.cg.shared.global [%0], [%1], 16;"
                 :: "r"(s), "l"(__cvta_generic_to_global(g)));
}
__device__ __forceinline__ void cp_commit() {
    asm volatile("cp.async.commit_group;");
}
__device__ __forceinline__ void ldmatrix_x4(uint32_t* r, uint32_t addr) {
    asm volatile("ldmatrix.sync.aligned.m8n8.x4.shared.b16 {%0,%1,%2,%3}, [%4];"
                 : "=r"(r[0]), "=r"(r[1]), "=r"(r[2]), "=r"(r[3]) : "r"(addr));
}
__device__ __forceinline__ void mma16816(float* d, const uint32_t* a, const uint32_t* b) {
    asm volatile(
        "mma.sync.aligned.m16n8k16.row.col.f32.bf16.bf16.f32 "
        "{%0,%1,%2,%3}, {%4,%5,%6,%7}, {%8,%9}, {%0,%1,%2,%3};"
        : "+f"(d[0]), "+f"(d[1]), "+f"(d[2]), "+f"(d[3])
        : "r"(a[0]), "r"(a[1]), "r"(a[2]), "r"(a[3]), "r"(b[0]), "r"(b[1]));
}
// 256B-row XOR swizzle: row r, 16B-chunk kh (0..15). Preserves 128B-half bit,
// XORs the low-3 chunk bits with row low-3 -> conflict-free LDSM & STS phases.
__device__ __forceinline__ uint32_t swz(int r, int kh) {
    return (uint32_t)(r * 256 + (((kh & 8) | ((kh ^ r) & 7)) << 4));
}

// ---------------- kernel 1: merged prep --------------------------------------
// [0,32768): keys fp32->bf16 ; [32768,33792): W1 bottom transpose ;
// [33792,34048): g_qh += q @ W1_top (+ b1 seeded by k0==0 blocks)
__global__ void prep_kernel(const float* __restrict__ keys,
                            const float* __restrict__ W1,
                            const float* __restrict__ b1,
                            const float* __restrict__ q) {
    int blk = blockIdx.x;
    int tid = threadIdx.x;
    if (blk < 32768) {
        size_t i = (size_t)blk * 256 + tid;     // one float4 per thread
        float4 v = reinterpret_cast<const float4*>(keys)[i];
        __nv_bfloat162 lo = __floats2bfloat162_rn(v.x, v.y);
        __nv_bfloat162 hi = __floats2bfloat162_rn(v.z, v.w);
        uint2 o;
        o.x = *reinterpret_cast<uint32_t*>(&lo);
        o.y = *reinterpret_cast<uint32_t*>(&hi);
        reinterpret_cast<uint2*>(g_keys_bf16)[i] = o;
    } else if (blk < 33792) {
        __shared__ float t[32][33];
        int bb = blk - 32768;
        int k0 = (bb & 31) * 32, n0 = (bb >> 5) * 32;
        int tx = tid & 31, ty = tid >> 5;       // 32 x 8
        for (int r = ty; r < 32; r += 8)
            t[r][tx] = W1[(size_t)(HID + k0 + r) * HID + n0 + tx];
        __syncthreads();
        for (int r = ty; r < 32; r += 8)
            g_w1bT[(size_t)(n0 + r) * HID + k0 + tx] = __float2bfloat16(t[tx][r]);
    } else {
        // qh k-split atomics: bb = (hc, kc); block 256 = 64 h x 4 ksub
        __shared__ float q_s[BATCH][64];
        int bb = blk - 33792;
        int h0 = (bb & 15) * 64, k0 = (bb >> 4) * 64;
        int hi = tid & 63, ksub = tid >> 6;
        for (int i = tid; i < BATCH * 64; i += 256)
            q_s[i >> 6][i & 63] = q[(i >> 6) * HID + k0 + (i & 63)];
        __syncthreads();
        float base = (k0 == 0 && ksub == 0) ? b1[h0 + hi] : 0.f;
        float acc[BATCH];
        #pragma unroll
        for (int b = 0; b < BATCH; b++) acc[b] = base;
        #pragma unroll
        for (int kk = 0; kk < 16; kk++) {
            int k = ksub * 16 + kk;
            float w = W1[(size_t)(k0 + k) * HID + h0 + hi];
            #pragma unroll
            for (int b = 0; b < BATCH; b++) acc[b] += q_s[b][k] * w;
        }
        #pragma unroll
        for (int b = 0; b < BATCH; b++)
            atomicAdd(&g_qh[b * HID + h0 + hi], acc[b]);
    }
}

// ---------------- kernel 2: fused GEMM + relu-dot -> scores (N-split grid) ---
// grid (256 m-tiles, 4 n-chunks). Each CTA: M=128 x one N-chunk of 256, full
// K=1024 in 8 K-tiles of 128 (256B rows, XOR swizzle), 2-stage double buffer.
// 8 warps as 2(M) x 4(N); warp tile 64 x 64. Partial scores via atomicAdd.
static constexpr int STAGES = 2;
static constexpr int A_TILE = 128 * 256;          // 32768
static constexpr int B_TILE = 256 * 256;          // 65536
static constexpr int OFF_B    = STAGES * A_TILE;            // 65536
static constexpr int OFF_QW   = OFF_B + STAGES * B_TILE;    // 196608 (256 qh + 256 w2)
static constexpr int OFF_SRED = OFF_QW + 2048;              // 198656
static constexpr int SMEM_BYTES = OFF_SRED + 512;           // 199168

__global__ void __launch_bounds__(256, 1) gemm_scores_kernel(const float* __restrict__ w2) {
    extern __shared__ char smem[];
    uint32_t sb = smem_to_u32(smem);
    const int tid = threadIdx.x, lane = tid & 31, wid = tid >> 5;
    const int wm = wid & 1, wn = wid >> 1;          // 2 M-groups x 4 N-groups
    const int m0 = blockIdx.x * 128;
    const int nq = blockIdx.y;                      // N-chunk [nq*256, nq*256+256)
    const int b  = m0 >> 11;
    float* qh_s = (float*)(smem + OFF_QW);
    float* w2_s = qh_s + 256;
    float* sred = (float*)(smem + OFF_SRED);
    if (tid < 128) sred[tid] = 0.f;
    if (tid < 256) {
        qh_s[tid] = g_qh[b * HID + nq * 256 + tid];
        w2_s[tid] = w2[nq * 256 + tid];
    }

    // K-tile t in [0,8)
    auto issue = [&](int t) {
        int buf = t & 1;
        uint32_t abase = sb + buf * A_TILE;
        uint32_t bbase = sb + OFF_B + buf * B_TILE;
        const __nv_bfloat16* Ag = g_keys_bf16 + (size_t)m0 * HID + t * 128;
        #pragma unroll
        for (int i = 0; i < 8; i++) {             // A: 128 rows x 16 chunks = 2048
            int c = tid + i * 256, r = c >> 4, kh = c & 15;
            cp16(abase + swz(r, kh), Ag + (size_t)r * HID + kh * 8);
        }
        const __nv_bfloat16* Bg = g_w1bT + (size_t)nq * 256 * HID + t * 128;
        #pragma unroll
        for (int i = 0; i < 16; i++) {            // B: 256 rows x 16 chunks = 4096
            int c = tid + i * 256, r = c >> 4, kh = c & 15;
            cp16(bbase + swz(r, kh), Bg + (size_t)r * HID + kh * 8);
        }
        cp_commit();
    };

    float d[4][8][4] = {};
    issue(0);
    #pragma unroll 1
    for (int t = 0; t < 8; t++) {
        asm volatile("cp.async.wait_group 0;");   // only group t pending here
        __syncthreads();
        if (t + 1 < 8) issue(t + 1);              // other buffer: WAR-safe after sync
        const uint32_t abase = sb + (t & 1) * A_TILE;
        const uint32_t bbase = sb + OFF_B + (t & 1) * B_TILE;
        #pragma unroll
        for (int ks = 0; ks < 8; ks++) {          // eight k16 steps per K-tile
            uint32_t a[4][4], bf[4][4];
            #pragma unroll
            for (int mt = 0; mt < 4; mt++) {
                int row = wm * 64 + mt * 16 + (lane & 7) + ((lane >> 3) & 1) * 8;
                int kh  = ks * 2 + ((lane >> 4) & 1);
                ldmatrix_x4(a[mt], abase + swz(row, kh));
            }
            #pragma unroll
            for (int ntp = 0; ntp < 4; ntp++) {
                int rown = wn * 64 + ntp * 16 + (lane & 7) + ((lane >> 4) & 1) * 8;
                int kh   = ks * 2 + ((lane >> 3) & 1);
                ldmatrix_x4(bf[ntp], bbase + swz(rown, kh));
            }
            #pragma unroll
            for (int ntp = 0; ntp < 4; ntp++) {
                #pragma unroll
                for (int mt = 0; mt < 4; mt++) {
                    mma16816(d[mt][2 * ntp],     a[mt], bf[ntp]);
                    mma16816(d[mt][2 * ntp + 1], a[mt], bf[ntp] + 2);
                }
            }
        }
    }
    // epilogue: fold relu(D + qh) . w2 into row sums
    float rowsum[8] = {0.f, 0.f, 0.f, 0.f, 0.f, 0.f, 0.f, 0.f};
    #pragma unroll
    for (int mt = 0; mt < 4; mt++)
    #pragma unroll
    for (int nt = 0; nt < 8; nt++) {
        int ncol = wn * 64 + nt * 8 + (lane & 3) * 2;
        float q0 = qh_s[ncol], q1 = qh_s[ncol + 1];
        float w0 = w2_s[ncol], w1 = w2_s[ncol + 1];
        const float* dd = d[mt][nt];
        rowsum[2 * mt + 0] += fmaxf(dd[0] + q0, 0.f) * w0 + fmaxf(dd[1] + q1, 0.f) * w1;
        rowsum[2 * mt + 1] += fmaxf(dd[2] + q0, 0.f) * w0 + fmaxf(dd[3] + q1, 0.f) * w1;
    }
    // reduce 4 lanes sharing a row, combine 4 N-warps via smem, add to global
    #pragma unroll
    for (int i = 0; i < 8; i++) {
        rowsum[i] += __shfl_xor_sync(0xffffffff, rowsum[i], 1);
        rowsum[i] += __shfl_xor_sync(0xffffffff, rowsum[i], 2);
    }
    __syncthreads();
    if ((lane & 3) == 0) {
        #pragma unroll
        for (int mt = 0; mt < 4; mt++) {
            int rb = wm * 64 + mt * 16 + (lane >> 2);
            atomicAdd(&sred[rb],     rowsum[2 * mt + 0]);
            atomicAdd(&sred[rb + 8], rowsum[2 * mt + 1]);
        }
    }
    __syncthreads();
    if (tid < 128) atomicAdd(&g_scores[m0 + tid], sred[tid]);
}

// ---------------- kernel 3: softmax -> alphas; zero ctx + next-replay state --
__global__ void softmax_kernel(float* __restrict__ alphas, float* __restrict__ ctx) {
    int b = blockIdx.x, tid = threadIdx.x;
    #pragma unroll
    for (int i = 0; i < 4; i++) ctx[b * HID + i * 256 + tid] = 0.f;
    __shared__ float red[256];
    float local[8];
    float mx = -1e30f;
    #pragma unroll
    for (int i = 0; i < 8; i++) {
        local[i] = g_scores[b * SEQ + i * 256 + tid];
        mx = fmaxf(mx, local[i]);
    }
    // zero accumulate targets for the NEXT launch/replay (last readers done)
    #pragma unroll
    for (int i = 0; i < 8; i++) g_scores[b * SEQ + i * 256 + tid] = 0.f;
    #pragma unroll
    for (int i = 0; i < 4; i++) g_qh[b * HID + i * 256 + tid] = 0.f;
    red[tid] = mx; __syncthreads();
    for (int s = 128; s > 0; s >>= 1) {
        if (tid < s) red[tid] = fmaxf(red[tid], red[tid + s]);
        __syncthreads();
    }
    mx = red[0]; __syncthreads();
    float sum = 0.f;
    #pragma unroll
    for (int i = 0; i < 8; i++) { local[i] = expf(local[i] - mx); sum += local[i]; }
    red[tid] = sum; __syncthreads();
    for (int s = 128; s > 0; s >>= 1) {
        if (tid < s) red[tid] += red[tid + s];
        __syncthreads();
    }
    float inv = 1.f / red[0];
    #pragma unroll
    for (int i = 0; i < 8; i++)
        alphas[b * SEQ + i * 256 + tid] = local[i] * inv;
}

// ---------------- kernel 4: context += alphas^T @ values (vectorized) --------
// grid (BATCH, SEQ/64). Each thread owns 4 h-columns via float4; one CTA step
// reads a full 4KB values row. Partials accumulated via atomicAdd.
__global__ void context_kernel(const float* __restrict__ values,
                               const float* __restrict__ alphas,
                               float* __restrict__ ctx) {
    int b = blockIdx.x;
    int s0 = blockIdx.y * 64;
    int tid = threadIdx.x;
    const float4* vp = reinterpret_cast<const float4*>(
        values + (size_t)b * SEQ * HID + (size_t)s0 * HID) + tid;
    const float* ap = alphas + b * SEQ + s0;
    float4 acc = make_float4(0.f, 0.f, 0.f, 0.f);
    #pragma unroll 8
    for (int s = 0; s < 64; s++) {
        float a = ap[s];
        float4 v = vp[(size_t)s * (HID / 4)];
        acc.x += a * v.x; acc.y += a * v.y; acc.z += a * v.z; acc.w += a * v.w;
    }
    float* cp = ctx + b * HID + tid * 4;
    atomicAdd(cp + 0, acc.x);
    atomicAdd(cp + 1, acc.y);
    atomicAdd(cp + 2, acc.z);
    atomicAdd(cp + 3, acc.w);
}

// ---------------- launch -----------------------------------------------------
extern "C" void kernel_launch(void* const* d_in, const int* in_sizes, int n_in,
                              void* d_out, int out_size) {
    const float* q      = (const float*)d_in[0];
    const float* keys   = (const float*)d_in[1];
    const float* values = (const float*)d_in[2];
    const float* W1     = (const float*)d_in[3];
    const float* b1     = (const float*)d_in[4];
    const float* W2     = (const float*)d_in[5];
    float* out = (float*)d_out;              // [0:16384) context, [16384:49152) alphas
    float* out_ctx    = out;
    float* out_alphas = out + BATCH * HID;

    cudaFuncSetAttribute(gemm_scores_kernel,
                         cudaFuncAttributeMaxDynamicSharedMemorySize, SMEM_BYTES);

    prep_kernel<<<34048, 256>>>(keys, W1, b1, q);
    gemm_scores_kernel<<<dim3(MROWS / 128, 4), 256, SMEM_BYTES>>>(W2);
    softmax_kernel<<<BATCH, 256>>>(out_alphas, out_ctx);
    context_kernel<<<dim3(BATCH, SEQ / 64), 256>>>(values, out_alphas, out_ctx);
}

// round 14
// speedup vs baseline: 1.0683x; 1.0683x over previous
#include <cuda_runtime.h>
#include <cuda_bf16.h>
#include <cstdint>

#define HID   1024
#define BATCH 16
#define SEQ   2048
#define MROWS (BATCH * SEQ)   // 32768

// ---------------- scratch (device globals: no allocation allowed) ------------
__device__ __nv_bfloat16 g_keys_bf16[(size_t)MROWS * HID];   // 64 MB
__device__ __nv_bfloat16 g_w1bT[(size_t)HID * HID];          // 2 MB, [N,K] = W1[H+k, n]
__device__ float         g_qh[BATCH * HID];                  // b1 + q @ W1_top
__device__ float         g_scores[MROWS];

// ---------------- helpers ----------------------------------------------------
__device__ __forceinline__ uint32_t smem_to_u32(const void* p) {
    uint32_t a;
    asm("{ .reg .u64 t; cvta.to.shared.u64 t, %1; cvt.u32.u64 %0, t; }" : "=r"(a) : "l"(p));
    return a;
}
__device__ __forceinline__ void cp16(uint32_t s, const void* g) {
    asm volatile("cp.async.cg.shared.global [%0], [%1], 16;"
                 :: "r"(s), "l"(__cvta_generic_to_global(g)));
}
__device__ __forceinline__ void cp_commit() {
    asm volatile("cp.async.commit_group;");
}
__device__ __forceinline__ void ldmatrix_x4(uint32_t* r, uint32_t addr) {
    asm volatile("ldmatrix.sync.aligned.m8n8.x4.shared.b16 {%0,%1,%2,%3}, [%4];"
                 : "=r"(r[0]), "=r"(r[1]), "=r"(r[2]), "=r"(r[3]) : "r"(addr));
}
__device__ __forceinline__ void mma16816(float* d, const uint32_t* a, const uint32_t* b) {
    asm volatile(
        "mma.sync.aligned.m16n8k16.row.col.f32.bf16.bf16.f32 "
        "{%0,%1,%2,%3}, {%4,%5,%6,%7}, {%8,%9}, {%0,%1,%2,%3};"
        : "+f"(d[0]), "+f"(d[1]), "+f"(d[2]), "+f"(d[3])
        : "r"(a[0]), "r"(a[1]), "r"(a[2]), "r"(a[3]), "r"(b[0]), "r"(b[1]));
}
// 128B-row XOR swizzle: row r, 16B-chunk kh (0..7) -> conflict-free LDSM & STS
__device__ __forceinline__ uint32_t swz(int r, int kh) {
    return (uint32_t)(r * 128 + ((kh ^ (r & 7)) << 4));
}

// ---------------- kernel 1: merged prep --------------------------------------
// [0,32768): keys fp32->bf16 ; [32768,33792): W1 bottom transpose ;
// [33792,33856): g_qh = b1 ; [33856,33984): g_scores = 0
__global__ void prep_kernel(const float* __restrict__ keys,
                            const float* __restrict__ W1,
                            const float* __restrict__ b1) {
    int blk = blockIdx.x;
    int tid = threadIdx.x;
    if (blk < 32768) {
        size_t i = (size_t)blk * 256 + tid;     // one float4 per thread
        float4 v = reinterpret_cast<const float4*>(keys)[i];
        __nv_bfloat162 lo = __floats2bfloat162_rn(v.x, v.y);
        __nv_bfloat162 hi = __floats2bfloat162_rn(v.z, v.w);
        uint2 o;
        o.x = *reinterpret_cast<uint32_t*>(&lo);
        o.y = *reinterpret_cast<uint32_t*>(&hi);
        reinterpret_cast<uint2*>(g_keys_bf16)[i] = o;
    } else if (blk < 33792) {
        __shared__ float t[32][33];
        int bb = blk - 32768;
        int k0 = (bb & 31) * 32, n0 = (bb >> 5) * 32;
        int tx = tid & 31, ty = tid >> 5;       // 32 x 8
        for (int r = ty; r < 32; r += 8)
            t[r][tx] = W1[(size_t)(HID + k0 + r) * HID + n0 + tx];
        __syncthreads();
        for (int r = ty; r < 32; r += 8)
            g_w1bT[(size_t)(n0 + r) * HID + k0 + tx] = __float2bfloat16(t[tx][r]);
    } else if (blk < 33856) {
        int g = (blk - 33792) * 256 + tid;
        g_qh[g] = b1[g & 1023];
    } else {
        g_scores[(blk - 33856) * 256 + tid] = 0.f;
    }
}

// ---------------- kernel 2: g_qh += q @ W1_top  (k-split atomics) ------------
__global__ void qh_kernel(const float* __restrict__ q, const float* __restrict__ W1) {
    __shared__ float q_s[BATCH][64];
    int h0 = blockIdx.x * 64, k0 = blockIdx.y * 64;
    int tid = threadIdx.x;
    int hi = tid & 63, ksub = tid >> 6;
    for (int i = tid; i < BATCH * 64; i += 256)
        q_s[i >> 6][i & 63] = q[(i >> 6) * HID + k0 + (i & 63)];
    __syncthreads();
    float acc[BATCH];
    #pragma unroll
    for (int b = 0; b < BATCH; b++) acc[b] = 0.f;
    #pragma unroll
    for (int kk = 0; kk < 16; kk++) {
        int k = ksub * 16 + kk;
        float w = W1[(size_t)(k0 + k) * HID + h0 + hi];
        #pragma unroll
        for (int b = 0; b < BATCH; b++) acc[b] += q_s[b][k] * w;
    }
    #pragma unroll
    for (int b = 0; b < BATCH; b++)
        atomicAdd(&g_qh[b * HID + h0 + hi], acc[b]);
}

// ---------------- kernel 3: fused GEMM + relu-dot -> scores ------------------
// Occupancy-2, full 64x64 warp tile: CTA = M=64 x N=256, 128 threads (4 warps
// as 1M x 4N). Grid (512 m-tiles, 4 n-chunks). K=1024 in 16 K-tiles of 64
// (128B rows, XOR swizzle), 2-stage double buffer. 2 CTAs/SM: one CTA's MMA
// stream covers the other's tile-boundary stalls.
static constexpr int A_TILE = 64 * 128;           // 8192
static constexpr int B_TILE = 256 * 128;          // 32768
static constexpr int OFF_B    = 2 * A_TILE;                 // 16384
static constexpr int OFF_QW   = OFF_B + 2 * B_TILE;         // 81920 (256 qh + 256 w2)
static constexpr int OFF_SRED = OFF_QW + 2048;              // 83968
static constexpr int SMEM_BYTES = OFF_SRED + 256;           // 84224

__global__ void __launch_bounds__(128, 2) gemm_scores_kernel(const float* __restrict__ w2) {
    extern __shared__ char smem[];
    uint32_t sb = smem_to_u32(smem);
    const int tid = threadIdx.x, lane = tid & 31, wn = tid >> 5;   // 4 N-warps
    const int m0 = blockIdx.x * 64;
    const int nq = blockIdx.y;                      // N-chunk [nq*256, nq*256+256)
    const int b  = m0 >> 11;
    float* qh_s = (float*)(smem + OFF_QW);
    float* w2_s = qh_s + 256;
    float* sred = (float*)(smem + OFF_SRED);
    if (tid < 64) sred[tid] = 0.f;
    for (int i = tid; i < 256; i += 128) {
        qh_s[i] = g_qh[b * HID + nq * 256 + i];
        w2_s[i] = w2[nq * 256 + i];
    }

    // K-tile t in [0,16), K-tile = 64 elems (128B rows)
    auto issue = [&](int t) {
        int buf = t & 1;
        uint32_t abase = sb + buf * A_TILE;
        uint32_t bbase = sb + OFF_B + buf * B_TILE;
        const __nv_bfloat16* Ag = g_keys_bf16 + (size_t)m0 * HID + t * 64;
        #pragma unroll
        for (int i = 0; i < 4; i++) {             // A: 64 rows x 8 chunks = 512
            int c = tid + i * 128, r = c >> 3, kh = c & 7;
            cp16(abase + swz(r, kh), Ag + (size_t)r * HID + kh * 8);
        }
        const __nv_bfloat16* Bg = g_w1bT + (size_t)nq * 256 * HID + t * 64;
        #pragma unroll
        for (int i = 0; i < 16; i++) {            // B: 256 rows x 8 chunks = 2048
            int c = tid + i * 128, r = c >> 3, kh = c & 7;
            cp16(bbase + swz(r, kh), Bg + (size_t)r * HID + kh * 8);
        }
        cp_commit();
    };

    float d[4][8][4] = {};
    issue(0);
    #pragma unroll 1
    for (int t = 0; t < 16; t++) {
        asm volatile("cp.async.wait_group 0;");   // only group t pending here
        __syncthreads();
        if (t + 1 < 16) issue(t + 1);             // other buffer: WAR-safe after sync
        const uint32_t abase = sb + (t & 1) * A_TILE;
        const uint32_t bbase = sb + OFF_B + (t & 1) * B_TILE;
        #pragma unroll
        for (int ks = 0; ks < 4; ks++) {          // four k16 steps per K-tile
            uint32_t a[4][4], bf[4][4];
            #pragma unroll
            for (int mt = 0; mt < 4; mt++) {
                int row = mt * 16 + (lane & 7) + ((lane >> 3) & 1) * 8;
                int kh  = ks * 2 + ((lane >> 4) & 1);
                ldmatrix_x4(a[mt], abase + swz(row, kh));
            }
            #pragma unroll
            for (int ntp = 0; ntp < 4; ntp++) {
                int rown = wn * 64 + ntp * 16 + (lane & 7) + ((lane >> 4) & 1) * 8;
                int kh   = ks * 2 + ((lane >> 3) & 1);
                ldmatrix_x4(bf[ntp], bbase + swz(rown, kh));
            }
            #pragma unroll
            for (int ntp = 0; ntp < 4; ntp++) {
                #pragma unroll
                for (int mt = 0; mt < 4; mt++) {
                    mma16816(d[mt][2 * ntp],     a[mt], bf[ntp]);
                    mma16816(d[mt][2 * ntp + 1], a[mt], bf[ntp] + 2);
                }
            }
        }
    }
    // epilogue: fold relu(D + qh) . w2 into row sums
    float rowsum[8] = {0.f, 0.f, 0.f, 0.f, 0.f, 0.f, 0.f, 0.f};
    #pragma unroll
    for (int mt = 0; mt < 4; mt++)
    #pragma unroll
    for (int nt = 0; nt < 8; nt++) {
        int ncol = wn * 64 + nt * 8 + (lane & 3) * 2;
        float q0 = qh_s[ncol], q1 = qh_s[ncol + 1];
        float w0 = w2_s[ncol], w1 = w2_s[ncol + 1];
        const float* dd = d[mt][nt];
        rowsum[2 * mt + 0] += fmaxf(dd[0] + q0, 0.f) * w0 + fmaxf(dd[1] + q1, 0.f) * w1;
        rowsum[2 * mt + 1] += fmaxf(dd[2] + q0, 0.f) * w0 + fmaxf(dd[3] + q1, 0.f) * w1;
    }
    // reduce 4 lanes sharing a row, combine 4 N-warps via smem, add to global
    #pragma unroll
    for (int i = 0; i < 8; i++) {
        rowsum[i] += __shfl_xor_sync(0xffffffff, rowsum[i], 1);
        rowsum[i] += __shfl_xor_sync(0xffffffff, rowsum[i], 2);
    }
    __syncthreads();
    if ((lane & 3) == 0) {
        #pragma unroll
        for (int mt = 0; mt < 4; mt++) {
            int rb = mt * 16 + (lane >> 2);
            atomicAdd(&sred[rb],     rowsum[2 * mt + 0]);
            atomicAdd(&sred[rb + 8], rowsum[2 * mt + 1]);
        }
    }
    __syncthreads();
    if (tid < 64) atomicAdd(&g_scores[m0 + tid], sred[tid]);
}

// ---------------- kernel 4: softmax over S per batch -> alphas (+ zero ctx) --
__global__ void softmax_kernel(float* __restrict__ alphas, float* __restrict__ ctx) {
    int b = blockIdx.x, tid = threadIdx.x;
    #pragma unroll
    for (int i = 0; i < 4; i++) ctx[b * HID + i * 256 + tid] = 0.f;
    __shared__ float red[256];
    float local[8];
    float mx = -1e30f;
    #pragma unroll
    for (int i = 0; i < 8; i++) {
        local[i] = g_scores[b * SEQ + i * 256 + tid];
        mx = fmaxf(mx, local[i]);
    }
    red[tid] = mx; __syncthreads();
    for (int s = 128; s > 0; s >>= 1) {
        if (tid < s) red[tid] = fmaxf(red[tid], red[tid + s]);
        __syncthreads();
    }
    mx = red[0]; __syncthreads();
    float sum = 0.f;
    #pragma unroll
    for (int i = 0; i < 8; i++) { local[i] = expf(local[i] - mx); sum += local[i]; }
    red[tid] = sum; __syncthreads();
    for (int s = 128; s > 0; s >>= 1) {
        if (tid < s) red[tid] += red[tid + s];
        __syncthreads();
    }
    float inv = 1.f / red[0];
    #pragma unroll
    for (int i = 0; i < 8; i++)
        alphas[b * SEQ + i * 256 + tid] = local[i] * inv;
}

// ---------------- kernel 5: context += alphas^T @ values (S-split atomics) ---
__global__ void context_kernel(const float* __restrict__ values,
                               const float* __restrict__ alphas,
                               float* __restrict__ ctx) {
    int b = blockIdx.y;
    int h = blockIdx.x * 256 + threadIdx.x;
    int s0 = blockIdx.z * 256;
    const float* vp = values + (size_t)b * SEQ * HID + (size_t)s0 * HID + h;
    const float* ap = alphas + b * SEQ + s0;
    float acc = 0.f;
    #pragma unroll 8
    for (int s = 0; s < 256; s++)
        acc += ap[s] * vp[(size_t)s * HID];
    atomicAdd(&ctx[b * HID + h], acc);
}

// ---------------- launch -----------------------------------------------------
extern "C" void kernel_launch(void* const* d_in, const int* in_sizes, int n_in,
                              void* d_out, int out_size) {
    const float* q      = (const float*)d_in[0];
    const float* keys   = (const float*)d_in[1];
    const float* values = (const float*)d_in[2];
    const float* W1     = (const float*)d_in[3];
    const float* b1     = (const float*)d_in[4];
    const float* W2     = (const float*)d_in[5];
    float* out = (float*)d_out;              // [0:16384) context, [16384:49152) alphas
    float* out_ctx    = out;
    float* out_alphas = out + BATCH * HID;

    cudaFuncSetAttribute(gemm_scores_kernel,
                         cudaFuncAttributeMaxDynamicSharedMemorySize, SMEM_BYTES);

    prep_kernel<<<33984, 256>>>(keys, W1, b1);
    qh_kernel<<<dim3(16, 16), 256>>>(q, W1);
    gemm_scores_kernel<<<dim3(MROWS / 64, 4), 128, SMEM_BYTES>>>(W2);
    softmax_kernel<<<BATCH, 256>>>(out_alphas, out_ctx);
    context_kernel<<<dim3(HID / 256, BATCH, SEQ / 256), 256>>>(values, out_alphas, out_ctx);
}

// round 15
// speedup vs baseline: 1.0985x; 1.0283x over previous
#include <cuda_runtime.h>
#include <cuda_bf16.h>
#include <cstdint>

#define HID   1024
#define BATCH 16
#define SEQ   2048
#define MROWS (BATCH * SEQ)   // 32768

// ---------------- scratch (device globals: no allocation allowed) ------------
__device__ __nv_bfloat16 g_keys_bf16[(size_t)MROWS * HID];   // 64 MB
__device__ __nv_bfloat16 g_w1bT[(size_t)HID * HID];          // 2 MB, [N,K] = W1[H+k, n]
__device__ float         g_qh[BATCH * HID];                  // b1 + q @ W1_top
__device__ float         g_scores[MROWS];

// ---------------- helpers ----------------------------------------------------
__device__ __forceinline__ uint32_t smem_to_u32(const void* p) {
    uint32_t a;
    asm("{ .reg .u64 t; cvta.to.shared.u64 t, %1; cvt.u32.u64 %0, t; }" : "=r"(a) : "l"(p));
    return a;
}
__device__ __forceinline__ void cp16(uint32_t s, const void* g) {
    asm volatile("cp.async.cg.shared.global [%0], [%1], 16;"
                 :: "r"(s), "l"(__cvta_generic_to_global(g)));
}
__device__ __forceinline__ void cp_commit() {
    asm volatile("cp.async.commit_group;");
}
__device__ __forceinline__ void ldmatrix_x4(uint32_t* r, uint32_t addr) {
    asm volatile("ldmatrix.sync.aligned.m8n8.x4.shared.b16 {%0,%1,%2,%3}, [%4];"
                 : "=r"(r[0]), "=r"(r[1]), "=r"(r[2]), "=r"(r[3]) : "r"(addr));
}
__device__ __forceinline__ void mma16816(float* d, const uint32_t* a, const uint32_t* b) {
    asm volatile(
        "mma.sync.aligned.m16n8k16.row.col.f32.bf16.bf16.f32 "
        "{%0,%1,%2,%3}, {%4,%5,%6,%7}, {%8,%9}, {%0,%1,%2,%3};"
        : "+f"(d[0]), "+f"(d[1]), "+f"(d[2]), "+f"(d[3])
        : "r"(a[0]), "r"(a[1]), "r"(a[2]), "r"(a[3]), "r"(b[0]), "r"(b[1]));
}
// 128B-row XOR swizzle: row r, 16B-chunk kh (0..7) -> conflict-free LDSM & STS
__device__ __forceinline__ uint32_t swz(int r, int kh) {
    return (uint32_t)(r * 128 + ((kh ^ (r & 7)) << 4));
}

// ---------------- kernel 1: merged prep --------------------------------------
// [0,32768): keys fp32->bf16 ; [32768,33792): W1 bottom transpose ;
// [33792,33856): g_qh = b1 ; [33856,33984): g_scores = 0
__global__ void prep_kernel(const float* __restrict__ keys,
                            const float* __restrict__ W1,
                            const float* __restrict__ b1) {
    int blk = blockIdx.x;
    int tid = threadIdx.x;
    if (blk < 32768) {
        size_t i = (size_t)blk * 256 + tid;     // one float4 per thread
        float4 v = reinterpret_cast<const float4*>(keys)[i];
        __nv_bfloat162 lo = __floats2bfloat162_rn(v.x, v.y);
        __nv_bfloat162 hi = __floats2bfloat162_rn(v.z, v.w);
        uint2 o;
        o.x = *reinterpret_cast<uint32_t*>(&lo);
        o.y = *reinterpret_cast<uint32_t*>(&hi);
        reinterpret_cast<uint2*>(g_keys_bf16)[i] = o;
    } else if (blk < 33792) {
        __shared__ float t[32][33];
        int bb = blk - 32768;
        int k0 = (bb & 31) * 32, n0 = (bb >> 5) * 32;
        int tx = tid & 31, ty = tid >> 5;       // 32 x 8
        for (int r = ty; r < 32; r += 8)
            t[r][tx] = W1[(size_t)(HID + k0 + r) * HID + n0 + tx];
        __syncthreads();
        for (int r = ty; r < 32; r += 8)
            g_w1bT[(size_t)(n0 + r) * HID + k0 + tx] = __float2bfloat16(t[tx][r]);
    } else if (blk < 33856) {
        int g = (blk - 33792) * 256 + tid;
        g_qh[g] = b1[g & 1023];
    } else {
        g_scores[(blk - 33856) * 256 + tid] = 0.f;
    }
}

// ---------------- kernel 2: g_qh += q @ W1_top  (k-split atomics) ------------
__global__ void qh_kernel(const float* __restrict__ q, const float* __restrict__ W1) {
    __shared__ float q_s[BATCH][64];
    int h0 = blockIdx.x * 64, k0 = blockIdx.y * 64;
    int tid = threadIdx.x;
    int hi = tid & 63, ksub = tid >> 6;
    for (int i = tid; i < BATCH * 64; i += 256)
        q_s[i >> 6][i & 63] = q[(i >> 6) * HID + k0 + (i & 63)];
    __syncthreads();
    float acc[BATCH];
    #pragma unroll
    for (int b = 0; b < BATCH; b++) acc[b] = 0.f;
    #pragma unroll
    for (int kk = 0; kk < 16; kk++) {
        int k = ksub * 16 + kk;
        float w = W1[(size_t)(k0 + k) * HID + h0 + hi];
        #pragma unroll
        for (int b = 0; b < BATCH; b++) acc[b] += q_s[b][k] * w;
    }
    #pragma unroll
    for (int b = 0; b < BATCH; b++)
        atomicAdd(&g_qh[b * HID + h0 + hi], acc[b]);
}

// ---------------- kernel 3: fused GEMM + relu-dot -> scores ------------------
// Occupancy-4, full 64x64 warp tile: CTA = M=64 x N=128, 64 threads (2 warps
// as 1M x 2N). Grid (512 m-tiles, 8 n-chunks). K=1024 in 16 K-tiles of 64
// (128B rows, XOR swizzle), 2-stage double buffer. 4 CTAs/SM: independent
// MMA streams cover each other's tile-boundary stalls.
static constexpr int A_TILE = 64 * 128;           // 8192
static constexpr int B_TILE = 128 * 128;          // 16384
static constexpr int OFF_B    = 2 * A_TILE;                 // 16384
static constexpr int OFF_QW   = OFF_B + 2 * B_TILE;         // 49152 (128 qh + 128 w2)
static constexpr int OFF_SRED = OFF_QW + 1024;              // 50176
static constexpr int SMEM_BYTES = OFF_SRED + 256;           // 50432

__global__ void __launch_bounds__(64, 4) gemm_scores_kernel(const float* __restrict__ w2) {
    extern __shared__ char smem[];
    uint32_t sb = smem_to_u32(smem);
    const int tid = threadIdx.x, lane = tid & 31, wn = tid >> 5;   // 2 N-warps
    const int m0 = blockIdx.x * 64;
    const int nq = blockIdx.y;                      // N-chunk [nq*128, nq*128+128)
    const int b  = m0 >> 11;
    float* qh_s = (float*)(smem + OFF_QW);
    float* w2_s = qh_s + 128;
    float* sred = (float*)(smem + OFF_SRED);
    sred[tid] = 0.f;
    for (int i = tid; i < 128; i += 64) {
        qh_s[i] = g_qh[b * HID + nq * 128 + i];
        w2_s[i] = w2[nq * 128 + i];
    }

    // K-tile t in [0,16), K-tile = 64 elems (128B rows)
    auto issue = [&](int t) {
        int buf = t & 1;
        uint32_t abase = sb + buf * A_TILE;
        uint32_t bbase = sb + OFF_B + buf * B_TILE;
        const __nv_bfloat16* Ag = g_keys_bf16 + (size_t)m0 * HID + t * 64;
        #pragma unroll
        for (int i = 0; i < 8; i++) {             // A: 64 rows x 8 chunks = 512
            int c = tid + i * 64, r = c >> 3, kh = c & 7;
            cp16(abase + swz(r, kh), Ag + (size_t)r * HID + kh * 8);
        }
        const __nv_bfloat16* Bg = g_w1bT + (size_t)nq * 128 * HID + t * 64;
        #pragma unroll
        for (int i = 0; i < 16; i++) {            // B: 128 rows x 8 chunks = 1024
            int c = tid + i * 64, r = c >> 3, kh = c & 7;
            cp16(bbase + swz(r, kh), Bg + (size_t)r * HID + kh * 8);
        }
        cp_commit();
    };

    float d[4][8][4] = {};
    issue(0);
    #pragma unroll 1
    for (int t = 0; t < 16; t++) {
        asm volatile("cp.async.wait_group 0;");   // only group t pending here
        __syncthreads();
        if (t + 1 < 16) issue(t + 1);             // other buffer: WAR-safe after sync
        const uint32_t abase = sb + (t & 1) * A_TILE;
        const uint32_t bbase = sb + OFF_B + (t & 1) * B_TILE;
        #pragma unroll
        for (int ks = 0; ks < 4; ks++) {          // four k16 steps per K-tile
            uint32_t a[4][4], bf[4][4];
            #pragma unroll
            for (int mt = 0; mt < 4; mt++) {
                int row = mt * 16 + (lane & 7) + ((lane >> 3) & 1) * 8;
                int kh  = ks * 2 + ((lane >> 4) & 1);
                ldmatrix_x4(a[mt], abase + swz(row, kh));
            }
            #pragma unroll
            for (int ntp = 0; ntp < 4; ntp++) {
                int rown = wn * 64 + ntp * 16 + (lane & 7) + ((lane >> 4) & 1) * 8;
                int kh   = ks * 2 + ((lane >> 3) & 1);
                ldmatrix_x4(bf[ntp], bbase + swz(rown, kh));
            }
            #pragma unroll
            for (int ntp = 0; ntp < 4; ntp++) {
                #pragma unroll
                for (int mt = 0; mt < 4; mt++) {
                    mma16816(d[mt][2 * ntp],     a[mt], bf[ntp]);
                    mma16816(d[mt][2 * ntp + 1], a[mt], bf[ntp] + 2);
                }
            }
        }
    }
    // epilogue: fold relu(D + qh) . w2 into row sums
    float rowsum[8] = {0.f, 0.f, 0.f, 0.f, 0.f, 0.f, 0.f, 0.f};
    #pragma unroll
    for (int mt = 0; mt < 4; mt++)
    #pragma unroll
    for (int nt = 0; nt < 8; nt++) {
        int ncol = wn * 64 + nt * 8 + (lane & 3) * 2;
        float q0 = qh_s[ncol], q1 = qh_s[ncol + 1];
        float w0 = w2_s[ncol], w1 = w2_s[ncol + 1];
        const float* dd = d[mt][nt];
        rowsum[2 * mt + 0] += fmaxf(dd[0] + q0, 0.f) * w0 + fmaxf(dd[1] + q1, 0.f) * w1;
        rowsum[2 * mt + 1] += fmaxf(dd[2] + q0, 0.f) * w0 + fmaxf(dd[3] + q1, 0.f) * w1;
    }
    // reduce 4 lanes sharing a row, combine 2 N-warps via smem, add to global
    #pragma unroll
    for (int i = 0; i < 8; i++) {
        rowsum[i] += __shfl_xor_sync(0xffffffff, rowsum[i], 1);
        rowsum[i] += __shfl_xor_sync(0xffffffff, rowsum[i], 2);
    }
    __syncthreads();
    if ((lane & 3) == 0) {
        #pragma unroll
        for (int mt = 0; mt < 4; mt++) {
            int rb = mt * 16 + (lane >> 2);
            atomicAdd(&sred[rb],     rowsum[2 * mt + 0]);
            atomicAdd(&sred[rb + 8], rowsum[2 * mt + 1]);
        }
    }
    __syncthreads();
    atomicAdd(&g_scores[m0 + tid], sred[tid]);
}

// ---------------- kernel 4: softmax over S per batch -> alphas (+ zero ctx) --
__global__ void softmax_kernel(float* __restrict__ alphas, float* __restrict__ ctx) {
    int b = blockIdx.x, tid = threadIdx.x;
    #pragma unroll
    for (int i = 0; i < 4; i++) ctx[b * HID + i * 256 + tid] = 0.f;
    __shared__ float red[256];
    float local[8];
    float mx = -1e30f;
    #pragma unroll
    for (int i = 0; i < 8; i++) {
        local[i] = g_scores[b * SEQ + i * 256 + tid];
        mx = fmaxf(mx, local[i]);
    }
    red[tid] = mx; __syncthreads();
    for (int s = 128; s > 0; s >>= 1) {
        if (tid < s) red[tid] = fmaxf(red[tid], red[tid + s]);
        __syncthreads();
    }
    mx = red[0]; __syncthreads();
    float sum = 0.f;
    #pragma unroll
    for (int i = 0; i < 8; i++) { local[i] = expf(local[i] - mx); sum += local[i]; }
    red[tid] = sum; __syncthreads();
    for (int s = 128; s > 0; s >>= 1) {
        if (tid < s) red[tid] += red[tid + s];
        __syncthreads();
    }
    float inv = 1.f / red[0];
    #pragma unroll
    for (int i = 0; i < 8; i++)
        alphas[b * SEQ + i * 256 + tid] = local[i] * inv;
}

// ---------------- kernel 5: context += alphas^T @ values (S-split atomics) ---
__global__ void context_kernel(const float* __restrict__ values,
                               const float* __restrict__ alphas,
                               float* __restrict__ ctx) {
    int b = blockIdx.y;
    int h = blockIdx.x * 256 + threadIdx.x;
    int s0 = blockIdx.z * 256;
    const float* vp = values + (size_t)b * SEQ * HID + (size_t)s0 * HID + h;
    const float* ap = alphas + b * SEQ + s0;
    float acc = 0.f;
    #pragma unroll 8
    for (int s = 0; s < 256; s++)
        acc += ap[s] * vp[(size_t)s * HID];
    atomicAdd(&ctx[b * HID + h], acc);
}

// ---------------- launch -----------------------------------------------------
extern "C" void kernel_launch(void* const* d_in, const int* in_sizes, int n_in,
                              void* d_out, int out_size) {
    const float* q      = (const float*)d_in[0];
    const float* keys   = (const float*)d_in[1];
    const float* values = (const float*)d_in[2];
    const float* W1     = (const float*)d_in[3];
    const float* b1     = (const float*)d_in[4];
    const float* W2     = (const float*)d_in[5];
    float* out = (float*)d_out;              // [0:16384) context, [16384:49152) alphas
    float* out_ctx    = out;
    float* out_alphas = out + BATCH * HID;

    cudaFuncSetAttribute(gemm_scores_kernel,
                         cudaFuncAttributeMaxDynamicSharedMemorySize, SMEM_BYTES);

    prep_kernel<<<33984, 256>>>(keys, W1, b1);
    qh_kernel<<<dim3(16, 16), 256>>>(q, W1);
    gemm_scores_kernel<<<dim3(MROWS / 64, 8), 64, SMEM_BYTES>>>(W2);
    softmax_kernel<<<BATCH, 256>>>(out_alphas, out_ctx);
    context_kernel<<<dim3(HID / 256, BATCH, SEQ / 256), 256>>>(values, out_alphas, out_ctx);
}